// round 8
// baseline (speedup 1.0000x reference)
#include <cuda_runtime.h>

#define BB 512
#define TT 1024
#define IDIM 64
#define HH 10
#define G4 40   // 4*H

typedef unsigned long long u64;

// Scratch (static device globals — no runtime allocation)
// XG layout per row: unit-interleaved pairs, u64 index p2 (0..19):
//   p2 = 2k   -> (i_k, f_k) preacts, PRE-SCALED by 0.5
//   p2 = 2k+1 -> (g_k, o_k) preacts, g unscaled, o PRE-SCALED by 0.5
__device__ float d_XG1[BB * TT * G4];
__device__ float d_XG2[BB * TT * G4];
__device__ float d_h1T[BB * HH];   // stores hbig = 2*h
__device__ float d_c1T[BB * HH];

// position p = 4*u + gt (gt: 0=i,1=f,2=g,3=o) -> original PyTorch gate row
__device__ __forceinline__ int old_gate(int p) {
    int u = p >> 2, gt = p & 3;
    return gt * HH + u;
}

__device__ __forceinline__ float tanh_ap(float x) {
    float y;
    asm("tanh.approx.f32 %0, %1;" : "=f"(y) : "f"(x));
    return y;
}

// ---- packed f32x2 helpers (sm_100+) ----
__device__ __forceinline__ u64 pk2(float lo, float hi) {
    u64 r; asm("mov.b64 %0, {%1, %2};" : "=l"(r) : "f"(lo), "f"(hi)); return r;
}
__device__ __forceinline__ void upk2(float& lo, float& hi, u64 v) {
    asm("mov.b64 {%0, %1}, %2;" : "=f"(lo), "=f"(hi) : "l"(v));
}
__device__ __forceinline__ u64 fma2(u64 a, u64 b, u64 c) {
    u64 d; asm("fma.rn.f32x2 %0, %1, %2, %3;" : "=l"(d) : "l"(a), "l"(b), "l"(c)); return d;
}
__device__ __forceinline__ u64 mul2(u64 a, u64 b) {
    u64 d; asm("mul.rn.f32x2 %0, %1, %2;" : "=l"(d) : "l"(a), "l"(b)); return d;
}
__device__ __forceinline__ u64 add2(u64 a, u64 b) {
    u64 d; asm("add.rn.f32x2 %0, %1, %2;" : "=l"(d) : "l"(a), "l"(b)); return d;
}

// ---------------------------------------------------------------------------
// K1: input GEMM -> d_XG1 with folded 0.5 scales.
// Thread: 8 rows x 5 gate-pairs; thread q owns pairs {q, q+4, ..., q+16}.
// smem weights pair-interleaved: sW[k*20 + p2] -> the 4 q-lanes of a group
// read 4 consecutive u64 (32B, one line, broadcast) => 1 wavefront per LDS.
// ---------------------------------------------------------------------------
__global__ __launch_bounds__(256) void k_inputgemm(
    const float* __restrict__ x,      // [B*T, 64]
    const float* __restrict__ W,      // [40, 64] (orig gate order)
    const float* __restrict__ b1,
    const float* __restrict__ b2)
{
    __shared__ u64 sW[64 * 20];       // sW[k*20+p2] = (s_lo*W[lo][k], 0.5*W[hi][k])
    __shared__ u64 sB[20];
    int tid = threadIdx.x;
    for (int e = tid; e < 64 * 20; e += 256) {
        int k = e / 20, p2 = e % 20;
        float slo = (p2 & 1) ? 1.0f : 0.5f;   // g unscaled; i scaled 0.5
        float lo = slo * W[old_gate(2 * p2) * 64 + k];
        float hi = 0.5f * W[old_gate(2 * p2 + 1) * 64 + k];   // f or o
        sW[e] = pk2(lo, hi);
    }
    for (int e = tid; e < 20; e += 256) {
        int p2 = e;
        float slo = (p2 & 1) ? 1.0f : 0.5f;
        int oA = old_gate(2 * p2), oB = old_gate(2 * p2 + 1);
        sB[e] = pk2(slo * (b1[oA] + b2[oA]), 0.5f * (b1[oB] + b2[oB]));
    }
    __syncthreads();

    int gt = blockIdx.x * 256 + tid;  // 262144 threads total
    int rowblk = gt >> 2;             // 65536 rowblocks of 8 rows
    int q = gt & 3;
    size_t r0 = (size_t)rowblk * 8;

    u64 acc[8][5];
#pragma unroll
    for (int r = 0; r < 8; r++)
#pragma unroll
        for (int j = 0; j < 5; j++) acc[r][j] = sB[q + 4 * j];

    const float4* x4 = reinterpret_cast<const float4*>(x);
#pragma unroll 2
    for (int kk = 0; kk < 16; kk++) {
        float4 xv[8];
#pragma unroll
        for (int r = 0; r < 8; r++) xv[r] = x4[(r0 + r) * 16 + kk];
#pragma unroll
        for (int c = 0; c < 4; c++) {
            u64 xd[8];
#pragma unroll
            for (int r = 0; r < 8; r++) {
                float xc = (c == 0) ? xv[r].x : (c == 1) ? xv[r].y
                         : (c == 2) ? xv[r].z : xv[r].w;
                xd[r] = pk2(xc, xc);
            }
#pragma unroll
            for (int j = 0; j < 5; j++) {
                u64 w = sW[(4 * kk + c) * 20 + q + 4 * j];
#pragma unroll
                for (int r = 0; r < 8; r++)
                    acc[r][j] = fma2(w, xd[r], acc[r][j]);
            }
        }
    }
#pragma unroll
    for (int r = 0; r < 8; r++) {
        u64* orow = reinterpret_cast<u64*>(d_XG1 + (r0 + r) * G4);
#pragma unroll
        for (int j = 0; j < 5; j++) orow[q + 4 * j] = acc[r][j];
    }
}

// ---------------------------------------------------------------------------
// Recurrence step (inlined function, not macro, to reduce compile pressure).
// hv: packed broadcast of hbig (=2h) for units 0..9; ab = ((.5i,.5f),(g,.5o)).
// Weights pre-scaled: wIF = 0.25*W(i|f), wGO = (0.5*Wg, 0.25*Wo).
// ---------------------------------------------------------------------------
struct ChainW {
    u64 wIF[10];
    u64 wGO[10];
};

__device__ __forceinline__ void step_core(
    const ChainW& W, const ulonglong2 ab, int lanebase,
    float& hb, float& cc, u64 (&hv)[10])
{
    u64 eIF = fma2(W.wIF[0], hv[0], ab.x);
    eIF = fma2(W.wIF[2], hv[2], eIF);
    eIF = fma2(W.wIF[4], hv[4], eIF);
    eIF = fma2(W.wIF[6], hv[6], eIF);
    eIF = fma2(W.wIF[8], hv[8], eIF);
    u64 oIF = mul2(W.wIF[1], hv[1]);
    oIF = fma2(W.wIF[3], hv[3], oIF);
    oIF = fma2(W.wIF[5], hv[5], oIF);
    oIF = fma2(W.wIF[7], hv[7], oIF);
    oIF = fma2(W.wIF[9], hv[9], oIF);
    u64 gIF = add2(eIF, oIF);
    u64 eGO = fma2(W.wGO[0], hv[0], ab.y);
    eGO = fma2(W.wGO[2], hv[2], eGO);
    eGO = fma2(W.wGO[4], hv[4], eGO);
    eGO = fma2(W.wGO[6], hv[6], eGO);
    eGO = fma2(W.wGO[8], hv[8], eGO);
    u64 oGO = mul2(W.wGO[1], hv[1]);
    oGO = fma2(W.wGO[3], hv[3], oGO);
    oGO = fma2(W.wGO[5], hv[5], oGO);
    oGO = fma2(W.wGO[7], hv[7], oGO);
    oGO = fma2(W.wGO[9], hv[9], oGO);
    u64 gGO = add2(eGO, oGO);
    float xi, xf, xg, xo;
    upk2(xi, xf, gIF);
    upk2(xg, xo, gGO);
    float ti = tanh_ap(xi);            // = 2*sigmoid(i)-1
    float tf = tanh_ap(xf);
    float tg = tanh_ap(xg);
    float to_ = tanh_ap(xo);
    float u_ = fmaf(tf, cc, cc);       // 2*sigmoid(f)*c
    float v_ = fmaf(ti, tg, tg);       // 2*sigmoid(i)*tanh(g)
    cc = 0.5f * (u_ + v_);
    float tc = tanh_ap(cc);
    hb = fmaf(to_, tc, tc);            // hbig = 2*sigmoid(o)*tanh(c)
#pragma unroll
    for (int j = 0; j < 10; j++) {
        float hj = __shfl_sync(0xffffffffu, hb, lanebase + j);
        hv[j] = pk2(hj, hj);
    }
}

// fused layer-2 input GEMM for one step: lane k2 computes all 4 gates of
// unit k2 (pre-scaled) from hv; store ulonglong2 = ((i,f),(g,o)).
__device__ __forceinline__ void step_gemm(
    const ChainW& W2, u64 b2IF, u64 b2GO, bool klow,
    const u64 (&hv)[10], ulonglong2* outp, int tidx)
{
    u64 aI = fma2(W2.wIF[0], hv[0], b2IF);
    aI = fma2(W2.wIF[1], hv[1], aI);
    aI = fma2(W2.wIF[2], hv[2], aI);
    aI = fma2(W2.wIF[3], hv[3], aI);
    aI = fma2(W2.wIF[4], hv[4], aI);
    aI = fma2(W2.wIF[5], hv[5], aI);
    aI = fma2(W2.wIF[6], hv[6], aI);
    aI = fma2(W2.wIF[7], hv[7], aI);
    aI = fma2(W2.wIF[8], hv[8], aI);
    aI = fma2(W2.wIF[9], hv[9], aI);
    u64 aG = fma2(W2.wGO[0], hv[0], b2GO);
    aG = fma2(W2.wGO[1], hv[1], aG);
    aG = fma2(W2.wGO[2], hv[2], aG);
    aG = fma2(W2.wGO[3], hv[3], aG);
    aG = fma2(W2.wGO[4], hv[4], aG);
    aG = fma2(W2.wGO[5], hv[5], aG);
    aG = fma2(W2.wGO[6], hv[6], aG);
    aG = fma2(W2.wGO[7], hv[7], aG);
    aG = fma2(W2.wGO[8], hv[8], aG);
    aG = fma2(W2.wGO[9], hv[9], aG);
    if (klow) {
        ulonglong2 v; v.x = aI; v.y = aG;
        outp[(size_t)tidx * HH] = v;
    }
}

__device__ __forceinline__ void load_chainw(
    ChainW& W, const float* Whh, int k2)
{
#pragma unroll
    for (int j = 0; j < 10; j++) {
        W.wIF[j] = pk2(0.25f * Whh[(0 * HH + k2) * HH + j],
                       0.25f * Whh[(1 * HH + k2) * HH + j]);
        W.wGO[j] = pk2(0.50f * Whh[(2 * HH + k2) * HH + j],
                       0.25f * Whh[(3 * HH + k2) * HH + j]);
    }
}

// ---------------------------------------------------------------------------
// k_lstm1: layer-1 recurrence for 4 batches/warp (2 lane-split halves x 2
// interleaved chains) + fused layer-2 input GEMM into d_XG2.
// ---------------------------------------------------------------------------
__global__ __launch_bounds__(32) void k_lstm1(
    const float* __restrict__ Whh,    // [40,10] layer-1
    const float* __restrict__ h0,
    const float* __restrict__ c0,
    const float* __restrict__ Wih2,   // [40,10]
    const float* __restrict__ bih2,
    const float* __restrict__ bhh2)
{
    int warp = blockIdx.x;            // 128 warps
    int lane = threadIdx.x;
    int half = lane >> 4;
    int k2 = (lane & 15) % HH;
    int lanebase = lane & 16;
    bool klow = (lane & 15) < HH;

    ChainW W1, W2;
    load_chainw(W1, Whh, k2);
    load_chainw(W2, Wih2, k2);
    u64 b2IF = pk2(0.5f * (bih2[0 * HH + k2] + bhh2[0 * HH + k2]),
                   0.5f * (bih2[1 * HH + k2] + bhh2[1 * HH + k2]));
    u64 b2GO = pk2(1.0f * (bih2[2 * HH + k2] + bhh2[2 * HH + k2]),
                   0.5f * (bih2[3 * HH + k2] + bhh2[3 * HH + k2]));

    int bA = warp * 4 + half;         // chain 0 batch
    int bB = warp * 4 + 2 + half;     // chain 1 batch
    float hbA = 2.0f * h0[bA * HH + k2], ccA = c0[bA * HH + k2];
    float hbB = 2.0f * h0[bB * HH + k2], ccB = c0[bB * HH + k2];
    u64 hvA[10], hvB[10];
#pragma unroll
    for (int j = 0; j < 10; j++) {
        float ha = __shfl_sync(0xffffffffu, hbA, lanebase + j);
        float hb = __shfl_sync(0xffffffffu, hbB, lanebase + j);
        hvA[j] = pk2(ha, ha);
        hvB[j] = pk2(hb, hb);
    }

    const ulonglong2* baseA =
        reinterpret_cast<const ulonglong2*>(d_XG1) + (size_t)bA * TT * HH + k2;
    const ulonglong2* baseB =
        reinterpret_cast<const ulonglong2*>(d_XG1) + (size_t)bB * TT * HH + k2;
    ulonglong2* outA =
        reinterpret_cast<ulonglong2*>(d_XG2) + (size_t)bA * TT * HH + k2;
    ulonglong2* outB =
        reinterpret_cast<ulonglong2*>(d_XG2) + (size_t)bB * TT * HH + k2;

    ulonglong2 cA = baseA[0], cB = baseB[0];
    ulonglong2 nA = baseA[HH], nB = baseB[HH];

    for (int t = 0; t < TT; t++) {
        step_core(W1, cA, lanebase, hbA, ccA, hvA);
        step_gemm(W2, b2IF, b2GO, klow, hvA, outA, t);
        step_core(W1, cB, lanebase, hbB, ccB, hvB);
        step_gemm(W2, b2IF, b2GO, klow, hvB, outB, t);
        cA = nA; cB = nB;
        if (t + 2 < TT) {
            nA = baseA[(size_t)(t + 2) * HH];
            nB = baseB[(size_t)(t + 2) * HH];
        }
    }
    if (klow) {
        d_h1T[bA * HH + k2] = hbA;   // store hbig; lstm2 loads raw
        d_c1T[bA * HH + k2] = ccA;
        d_h1T[bB * HH + k2] = hbB;
        d_c1T[bB * HH + k2] = ccB;
    }
}

// ---------------------------------------------------------------------------
// k_lstm2: layer-2 recurrence + fused FC chain.
// out[b] = sum_t fc2w[t]*(h2[b,t].fc1w) + fc1b*sum_t fc2w[t] + fc2b
// ---------------------------------------------------------------------------
__global__ __launch_bounds__(32) void k_lstm2(
    const float* __restrict__ Whh,    // [40,10] layer-2
    const float* __restrict__ fc1w,
    const float* __restrict__ fc1b,
    const float* __restrict__ fc2w,   // [1024]
    const float* __restrict__ fc2b,
    float* __restrict__ out)
{
    int warp = blockIdx.x;
    int lane = threadIdx.x;
    int half = lane >> 4;
    int k2 = (lane & 15) % HH;
    int lanebase = lane & 16;
    bool klow = (lane & 15) < HH;

    ChainW W1;
    load_chainw(W1, Whh, k2);

    int bA = warp * 4 + half;
    int bB = warp * 4 + 2 + half;
    float hbA = d_h1T[bA * HH + k2], ccA = d_c1T[bA * HH + k2];
    float hbB = d_h1T[bB * HH + k2], ccB = d_c1T[bB * HH + k2];
    u64 hvA[10], hvB[10];
#pragma unroll
    for (int j = 0; j < 10; j++) {
        float ha = __shfl_sync(0xffffffffu, hbA, lanebase + j);
        float hb = __shfl_sync(0xffffffffu, hbB, lanebase + j);
        hvA[j] = pk2(ha, ha);
        hvB[j] = pk2(hb, hb);
    }

    const ulonglong2* baseA =
        reinterpret_cast<const ulonglong2*>(d_XG2) + (size_t)bA * TT * HH + k2;
    const ulonglong2* baseB =
        reinterpret_cast<const ulonglong2*>(d_XG2) + (size_t)bB * TT * HH + k2;

    ulonglong2 cA = baseA[0], cB = baseB[0];
    ulonglong2 nA = baseA[HH], nB = baseB[HH];

    float accA = 0.0f, accB = 0.0f;   // sum_t hbig * fc2w[t]
    float s2 = 0.0f;                  // sum_t fc2w[t]

    for (int t = 0; t < TT; t++) {
        float fw = __ldg(fc2w + t);
        step_core(W1, cA, lanebase, hbA, ccA, hvA);
        accA = fmaf(hbA, fw, accA);
        step_core(W1, cB, lanebase, hbB, ccB, hvB);
        accB = fmaf(hbB, fw, accB);
        s2 += fw;
        cA = nA; cB = nB;
        if (t + 2 < TT) {
            nA = baseA[(size_t)(t + 2) * HH];
            nB = baseB[(size_t)(t + 2) * HH];
        }
    }

    // acc holds 2*sum(h*fw) -> scale fc1w by 0.5. Reduce within 16-lane group.
    float fscale = klow ? 0.5f * fc1w[k2] : 0.0f;
    float vA = accA * fscale;
    float vB = accB * fscale;
#pragma unroll
    for (int off = 8; off > 0; off >>= 1) {
        vA += __shfl_xor_sync(0xffffffffu, vA, off);
        vB += __shfl_xor_sync(0xffffffffu, vB, off);
    }
    if ((lane & 15) == 0) {
        float tail = fc1b[0] * s2 + fc2b[0];
        out[bA] = vA + tail;
        out[bB] = vB + tail;
    }
}

// ---------------------------------------------------------------------------
extern "C" void kernel_launch(void* const* d_in, const int* in_sizes, int n_in,
                              void* d_out, int out_size)
{
    const float* x    = (const float*)d_in[0];
    const float* h0   = (const float*)d_in[1];
    const float* c0   = (const float*)d_in[2];
    const float* Wih1 = (const float*)d_in[3];
    const float* Whh1 = (const float*)d_in[4];
    const float* bih1 = (const float*)d_in[5];
    const float* bhh1 = (const float*)d_in[6];
    const float* Wih2 = (const float*)d_in[7];
    const float* Whh2 = (const float*)d_in[8];
    const float* bih2 = (const float*)d_in[9];
    const float* bhh2 = (const float*)d_in[10];
    const float* fc1w = (const float*)d_in[11];
    const float* fc1b = (const float*)d_in[12];
    const float* fc2w = (const float*)d_in[13];
    const float* fc2b = (const float*)d_in[14];
    float* out = (float*)d_out;

    k_inputgemm<<<1024, 256>>>(x, Wih1, bih1, bhh1);       // 8 rows/thread
    k_lstm1<<<128, 32>>>(Whh1, h0, c0, Wih2, bih2, bhh2);  // 4 batches/warp
    k_lstm2<<<128, 32>>>(Whh2, fc1w, fc1b, fc2w, fc2b, out);
}

// round 9
// speedup vs baseline: 3.3620x; 3.3620x over previous
#include <cuda_runtime.h>

#define BB 512
#define TT 1024
#define IDIM 64
#define HH 10
#define G4 40   // 4*H

typedef unsigned long long u64;

// Scratch (static device globals — no runtime allocation)
// XG layout per row: unit-interleaved pairs, u64 index p2 (0..19):
//   p2 = 2k   -> (i_k, f_k) preacts, PRE-SCALED by 0.5
//   p2 = 2k+1 -> (g_k, o_k) preacts, g unscaled, o PRE-SCALED by 0.5
__device__ float d_XG1[BB * TT * G4];
__device__ float d_XG2[BB * TT * G4];
__device__ float d_h1T[BB * HH];   // stores hbig = 2*h
__device__ float d_c1T[BB * HH];

// position p = 4*u + gt (gt: 0=i,1=f,2=g,3=o) -> original PyTorch gate row
__device__ __forceinline__ int old_gate(int p) {
    int u = p >> 2, gt = p & 3;
    return gt * HH + u;
}

__device__ __forceinline__ float tanh_ap(float x) {
    float y;
    asm("tanh.approx.f32 %0, %1;" : "=f"(y) : "f"(x));
    return y;
}

// ---- packed f32x2 helpers (sm_100+) ----
__device__ __forceinline__ u64 pk2(float lo, float hi) {
    u64 r; asm("mov.b64 %0, {%1, %2};" : "=l"(r) : "f"(lo), "f"(hi)); return r;
}
__device__ __forceinline__ void upk2(float& lo, float& hi, u64 v) {
    asm("mov.b64 {%0, %1}, %2;" : "=f"(lo), "=f"(hi) : "l"(v));
}
__device__ __forceinline__ u64 fma2(u64 a, u64 b, u64 c) {
    u64 d; asm("fma.rn.f32x2 %0, %1, %2, %3;" : "=l"(d) : "l"(a), "l"(b), "l"(c)); return d;
}
__device__ __forceinline__ u64 mul2(u64 a, u64 b) {
    u64 d; asm("mul.rn.f32x2 %0, %1, %2;" : "=l"(d) : "l"(a), "l"(b)); return d;
}
__device__ __forceinline__ u64 add2(u64 a, u64 b) {
    u64 d; asm("add.rn.f32x2 %0, %1, %2;" : "=l"(d) : "l"(a), "l"(b)); return d;
}

// ---------------------------------------------------------------------------
// K1 (unchanged from R8 — measured 98us): input GEMM -> d_XG1, folded scales.
// Thread: 8 rows x 5 gate-pairs; thread q owns pairs {q, q+4, ..., q+16}.
// ---------------------------------------------------------------------------
__global__ __launch_bounds__(256) void k_inputgemm(
    const float* __restrict__ x,      // [B*T, 64]
    const float* __restrict__ W,      // [40, 64] (orig gate order)
    const float* __restrict__ b1,
    const float* __restrict__ b2)
{
    __shared__ u64 sW[64 * 20];       // sW[k*20+p2] = (s_lo*W[lo][k], 0.5*W[hi][k])
    __shared__ u64 sB[20];
    int tid = threadIdx.x;
    for (int e = tid; e < 64 * 20; e += 256) {
        int k = e / 20, p2 = e % 20;
        float slo = (p2 & 1) ? 1.0f : 0.5f;   // g unscaled; i scaled 0.5
        float lo = slo * W[old_gate(2 * p2) * 64 + k];
        float hi = 0.5f * W[old_gate(2 * p2 + 1) * 64 + k];   // f or o
        sW[e] = pk2(lo, hi);
    }
    for (int e = tid; e < 20; e += 256) {
        int p2 = e;
        float slo = (p2 & 1) ? 1.0f : 0.5f;
        int oA = old_gate(2 * p2), oB = old_gate(2 * p2 + 1);
        sB[e] = pk2(slo * (b1[oA] + b2[oA]), 0.5f * (b1[oB] + b2[oB]));
    }
    __syncthreads();

    int gt = blockIdx.x * 256 + tid;  // 262144 threads total
    int rowblk = gt >> 2;             // 65536 rowblocks of 8 rows
    int q = gt & 3;
    size_t r0 = (size_t)rowblk * 8;

    u64 acc[8][5];
#pragma unroll
    for (int r = 0; r < 8; r++)
#pragma unroll
        for (int j = 0; j < 5; j++) acc[r][j] = sB[q + 4 * j];

    const float4* x4 = reinterpret_cast<const float4*>(x);
#pragma unroll 2
    for (int kk = 0; kk < 16; kk++) {
        float4 xv[8];
#pragma unroll
        for (int r = 0; r < 8; r++) xv[r] = x4[(r0 + r) * 16 + kk];
#pragma unroll
        for (int c = 0; c < 4; c++) {
            u64 xd[8];
#pragma unroll
            for (int r = 0; r < 8; r++) {
                float xc = (c == 0) ? xv[r].x : (c == 1) ? xv[r].y
                         : (c == 2) ? xv[r].z : xv[r].w;
                xd[r] = pk2(xc, xc);
            }
#pragma unroll
            for (int j = 0; j < 5; j++) {
                u64 w = sW[(4 * kk + c) * 20 + q + 4 * j];
#pragma unroll
                for (int r = 0; r < 8; r++)
                    acc[r][j] = fma2(w, xd[r], acc[r][j]);
            }
        }
    }
#pragma unroll
    for (int r = 0; r < 8; r++) {
        u64* orow = reinterpret_cast<u64*>(d_XG1 + (r0 + r) * G4);
#pragma unroll
        for (int j = 0; j < 5; j++) orow[q + 4 * j] = acc[r][j];
    }
}

// ---------------------------------------------------------------------------
// Recurrence step (R8 folded math, R4 scheduling). hv = packed broadcast of
// hbig (=2h) for units 0..9; ab = ((.5i,.5f),(g,.5o)) preacts.
// Weights pre-scaled: wIF = 0.25*W(i|f), wGO = (0.5*Wg, 0.25*Wo).
// ---------------------------------------------------------------------------
#define STEP_CORE(hb, cc, hv, ab)                                             \
    {                                                                         \
        u64 eIF = fma2(wIF[0], hv[0], (ab).x);                                \
        eIF = fma2(wIF[2], hv[2], eIF);                                       \
        eIF = fma2(wIF[4], hv[4], eIF);                                       \
        eIF = fma2(wIF[6], hv[6], eIF);                                       \
        eIF = fma2(wIF[8], hv[8], eIF);                                       \
        u64 oIF = mul2(wIF[1], hv[1]);                                        \
        oIF = fma2(wIF[3], hv[3], oIF);                                       \
        oIF = fma2(wIF[5], hv[5], oIF);                                       \
        oIF = fma2(wIF[7], hv[7], oIF);                                       \
        oIF = fma2(wIF[9], hv[9], oIF);                                       \
        u64 gIF = add2(eIF, oIF);                                             \
        u64 eGO = fma2(wGO[0], hv[0], (ab).y);                                \
        eGO = fma2(wGO[2], hv[2], eGO);                                       \
        eGO = fma2(wGO[4], hv[4], eGO);                                       \
        eGO = fma2(wGO[6], hv[6], eGO);                                       \
        eGO = fma2(wGO[8], hv[8], eGO);                                       \
        u64 oGO = mul2(wGO[1], hv[1]);                                        \
        oGO = fma2(wGO[3], hv[3], oGO);                                       \
        oGO = fma2(wGO[5], hv[5], oGO);                                       \
        oGO = fma2(wGO[7], hv[7], oGO);                                       \
        oGO = fma2(wGO[9], hv[9], oGO);                                       \
        u64 gGO = add2(eGO, oGO);                                             \
        float xi, xf, xg, xo;                                                 \
        upk2(xi, xf, gIF);                                                    \
        upk2(xg, xo, gGO);                                                    \
        float ti = tanh_ap(xi);   /* = 2*sigmoid(i)-1 */                      \
        float tf = tanh_ap(xf);                                               \
        float tg = tanh_ap(xg);                                               \
        float to_ = tanh_ap(xo);                                              \
        float u_ = fmaf(tf, cc, cc);      /* 2*sigmoid(f)*c   */              \
        float v_ = fmaf(ti, tg, tg);      /* 2*sigmoid(i)*tg  */              \
        cc = 0.5f * (u_ + v_);                                                \
        float tc = tanh_ap(cc);                                               \
        hb = fmaf(to_, tc, tc);           /* hbig = 2*sigmoid(o)*tanh(c) */   \
        _Pragma("unroll")                                                     \
        for (int j = 0; j < 10; j++) {                                        \
            float hj = __shfl_sync(0xffffffffu, hb, j);                       \
            hv[j] = pk2(hj, hj);                                              \
        }                                                                     \
    }

// fused layer-2 input GEMM: lane k2 (<10) computes all 4 gates of unit k2,
// pre-scaled for the XG convention; stores ulonglong2 = ((i,f),(g,o)).
#define STEP_GEMM(hv, outp, tidx)                                             \
    {                                                                         \
        u64 aI = fma2(w2IF[0], hv[0], b2IF);                                  \
        aI = fma2(w2IF[1], hv[1], aI);                                        \
        aI = fma2(w2IF[2], hv[2], aI);                                        \
        aI = fma2(w2IF[3], hv[3], aI);                                        \
        aI = fma2(w2IF[4], hv[4], aI);                                        \
        aI = fma2(w2IF[5], hv[5], aI);                                        \
        aI = fma2(w2IF[6], hv[6], aI);                                        \
        aI = fma2(w2IF[7], hv[7], aI);                                        \
        aI = fma2(w2IF[8], hv[8], aI);                                        \
        aI = fma2(w2IF[9], hv[9], aI);                                        \
        u64 aG = fma2(w2GO[0], hv[0], b2GO);                                  \
        aG = fma2(w2GO[1], hv[1], aG);                                        \
        aG = fma2(w2GO[2], hv[2], aG);                                        \
        aG = fma2(w2GO[3], hv[3], aG);                                        \
        aG = fma2(w2GO[4], hv[4], aG);                                        \
        aG = fma2(w2GO[5], hv[5], aG);                                        \
        aG = fma2(w2GO[6], hv[6], aG);                                        \
        aG = fma2(w2GO[7], hv[7], aG);                                        \
        aG = fma2(w2GO[8], hv[8], aG);                                        \
        aG = fma2(w2GO[9], hv[9], aG);                                        \
        if (klow) {                                                           \
            ulonglong2 v; v.x = aI; v.y = aG;                                 \
            (outp)[(size_t)(tidx) * HH] = v;                                  \
        }                                                                     \
    }

// ---------------------------------------------------------------------------
// k_lstm1: ONE batch per warp (R4-proven config), 512 warps as 128x128.
// Layer-1 recurrence + fused layer-2 input GEMM into d_XG2.
// ---------------------------------------------------------------------------
__global__ __launch_bounds__(128) void k_lstm1(
    const float* __restrict__ Whh,    // [40,10] layer-1
    const float* __restrict__ h0,
    const float* __restrict__ c0,
    const float* __restrict__ Wih2,   // [40,10]
    const float* __restrict__ bih2,
    const float* __restrict__ bhh2)
{
    int warp = (blockIdx.x * blockDim.x + threadIdx.x) >> 5;
    int lane = threadIdx.x & 31;
    int k2 = lane % HH;
    bool klow = lane < HH;

    u64 wIF[10], wGO[10], w2IF[10], w2GO[10];
#pragma unroll
    for (int j = 0; j < 10; j++) {
        wIF[j] = pk2(0.25f * Whh[(0 * HH + k2) * HH + j],
                     0.25f * Whh[(1 * HH + k2) * HH + j]);
        wGO[j] = pk2(0.50f * Whh[(2 * HH + k2) * HH + j],
                     0.25f * Whh[(3 * HH + k2) * HH + j]);
        w2IF[j] = pk2(0.25f * Wih2[(0 * HH + k2) * HH + j],
                      0.25f * Wih2[(1 * HH + k2) * HH + j]);
        w2GO[j] = pk2(0.50f * Wih2[(2 * HH + k2) * HH + j],
                      0.25f * Wih2[(3 * HH + k2) * HH + j]);
    }
    u64 b2IF = pk2(0.5f * (bih2[0 * HH + k2] + bhh2[0 * HH + k2]),
                   0.5f * (bih2[1 * HH + k2] + bhh2[1 * HH + k2]));
    u64 b2GO = pk2(1.0f * (bih2[2 * HH + k2] + bhh2[2 * HH + k2]),
                   0.5f * (bih2[3 * HH + k2] + bhh2[3 * HH + k2]));

    float hb = 2.0f * h0[warp * HH + k2];
    float cc = c0[warp * HH + k2];
    u64 hv[10];
#pragma unroll
    for (int j = 0; j < 10; j++) {
        float hj = __shfl_sync(0xffffffffu, hb, j);
        hv[j] = pk2(hj, hj);
    }

    const ulonglong2* base =
        reinterpret_cast<const ulonglong2*>(d_XG1) + (size_t)warp * TT * HH + k2;
    ulonglong2* outp =
        reinterpret_cast<ulonglong2*>(d_XG2) + (size_t)warp * TT * HH + k2;

    ulonglong2 cur[4], nxt[4];
#pragma unroll
    for (int i = 0; i < 4; i++) cur[i] = base[i * HH];
#pragma unroll
    for (int i = 0; i < 4; i++) nxt[i] = base[(4 + i) * HH];

    for (int t = 0; t < TT; t += 4) {
        ulonglong2 pf[4];
        if (t + 8 < TT) {
#pragma unroll
            for (int i = 0; i < 4; i++) pf[i] = base[(size_t)(t + 8 + i) * HH];
        }
#pragma unroll
        for (int s = 0; s < 4; s++) {
            STEP_CORE(hb, cc, hv, cur[s]);
            STEP_GEMM(hv, outp, t + s);
        }
#pragma unroll
        for (int i = 0; i < 4; i++) { cur[i] = nxt[i]; nxt[i] = pf[i]; }
    }
    if (klow) {
        d_h1T[warp * HH + k2] = hb;    // store hbig; lstm2 loads raw
        d_c1T[warp * HH + k2] = cc;
    }
}

// ---------------------------------------------------------------------------
// k_lstm2: ONE batch per warp; layer-2 recurrence + fused FC chain.
// out[b] = 0.5*sum_t fc2w[t]*(hbig . fc1w) + fc1b*sum_t fc2w[t] + fc2b
// ---------------------------------------------------------------------------
__global__ __launch_bounds__(128) void k_lstm2(
    const float* __restrict__ Whh,    // [40,10] layer-2
    const float* __restrict__ fc1w,
    const float* __restrict__ fc1b,
    const float* __restrict__ fc2w,   // [1024]
    const float* __restrict__ fc2b,
    float* __restrict__ out)
{
    int warp = (blockIdx.x * blockDim.x + threadIdx.x) >> 5;
    int lane = threadIdx.x & 31;
    int k2 = lane % HH;
    bool klow = lane < HH;

    u64 wIF[10], wGO[10];
#pragma unroll
    for (int j = 0; j < 10; j++) {
        wIF[j] = pk2(0.25f * Whh[(0 * HH + k2) * HH + j],
                     0.25f * Whh[(1 * HH + k2) * HH + j]);
        wGO[j] = pk2(0.50f * Whh[(2 * HH + k2) * HH + j],
                     0.25f * Whh[(3 * HH + k2) * HH + j]);
    }

    float hb = d_h1T[warp * HH + k2];
    float cc = d_c1T[warp * HH + k2];
    u64 hv[10];
#pragma unroll
    for (int j = 0; j < 10; j++) {
        float hj = __shfl_sync(0xffffffffu, hb, j);
        hv[j] = pk2(hj, hj);
    }

    const ulonglong2* base =
        reinterpret_cast<const ulonglong2*>(d_XG2) + (size_t)warp * TT * HH + k2;
    const float4* f4 = reinterpret_cast<const float4*>(fc2w);

    ulonglong2 cur[4], nxt[4];
#pragma unroll
    for (int i = 0; i < 4; i++) cur[i] = base[i * HH];
#pragma unroll
    for (int i = 0; i < 4; i++) nxt[i] = base[(4 + i) * HH];

    float acc = 0.0f;   // sum_t hbig * fc2w[t]
    float s2 = 0.0f;    // sum_t fc2w[t]

    for (int t = 0; t < TT; t += 4) {
        ulonglong2 pf[4];
        if (t + 8 < TT) {
#pragma unroll
            for (int i = 0; i < 4; i++) pf[i] = base[(size_t)(t + 8 + i) * HH];
        }
        float4 fwv = __ldg(&f4[t >> 2]);
        float fw4[4] = {fwv.x, fwv.y, fwv.z, fwv.w};
#pragma unroll
        for (int s = 0; s < 4; s++) {
            STEP_CORE(hb, cc, hv, cur[s]);
            acc = fmaf(hb, fw4[s], acc);
            s2 += fw4[s];
        }
#pragma unroll
        for (int i = 0; i < 4; i++) { cur[i] = nxt[i]; nxt[i] = pf[i]; }
    }

    // acc holds 2*sum(h*fw) -> scale fc1w by 0.5.
    float val = klow ? acc * (0.5f * fc1w[k2]) : 0.0f;
#pragma unroll
    for (int off = 16; off > 0; off >>= 1)
        val += __shfl_xor_sync(0xffffffffu, val, off);
    if (lane == 0)
        out[warp] = val + fc1b[0] * s2 + fc2b[0];
}

// ---------------------------------------------------------------------------
extern "C" void kernel_launch(void* const* d_in, const int* in_sizes, int n_in,
                              void* d_out, int out_size)
{
    const float* x    = (const float*)d_in[0];
    const float* h0   = (const float*)d_in[1];
    const float* c0   = (const float*)d_in[2];
    const float* Wih1 = (const float*)d_in[3];
    const float* Whh1 = (const float*)d_in[4];
    const float* bih1 = (const float*)d_in[5];
    const float* bhh1 = (const float*)d_in[6];
    const float* Wih2 = (const float*)d_in[7];
    const float* Whh2 = (const float*)d_in[8];
    const float* bih2 = (const float*)d_in[9];
    const float* bhh2 = (const float*)d_in[10];
    const float* fc1w = (const float*)d_in[11];
    const float* fc1b = (const float*)d_in[12];
    const float* fc2w = (const float*)d_in[13];
    const float* fc2b = (const float*)d_in[14];
    float* out = (float*)d_out;

    k_inputgemm<<<1024, 256>>>(x, Wih1, bih1, bhh1);       // 8 rows/thread
    k_lstm1<<<128, 128>>>(Whh1, h0, c0, Wih2, bih2, bhh2); // 1 batch/warp (R4-proven)
    k_lstm2<<<128, 128>>>(Whh2, fc1w, fc1b, fc2w, fc2b, out);
}